// round 14
// baseline (speedup 1.0000x reference)
#include <cuda_runtime.h>
#include <cuda_bf16.h>
#include <math.h>
#include <stdint.h>

// LSTM: T=1024, B=64, I=256, H=512, O=5
// out = [outputs (T*B*O) | h_T (B*H) | c_T (B*H)]

#define TT 1024
#define BB 64
#define II 256
#define HH 512
#define G4 2048
#define OO 5
#define REC_CTAS 64

// ---- device scratch ----
__device__ float g_xgT[(size_t)TT * G4 * BB];     // [T][4H][B]
__device__ float g_hsT[(size_t)TT * HH * BB];     // [T][H][B]
// Whh split-bf16 per rec-CTA tile: [(m*2+copy)*32 + r][512], r = gate*8+u
__device__ __nv_bfloat16 g_Abf[64 * 2 * 32 * 512];
// h split-bf16, PADDED ldmatrix-ready, ping-pong: [pp 2][copy 2][k 512][72]
__device__ __align__(16) __nv_bfloat16 g_hbf[2 * 2 * 512 * 72];
// Wih split-bf16: [copy 2][R 2048][k 256]
__device__ __nv_bfloat16 g_wihbf[2 * 2048 * 256];
// x split-bf16, transposed per t: [t 1024][copy 2][k 256][b 64]
__device__ __nv_bfloat16 g_xbf[(size_t)1024 * 2 * 256 * 64];
__device__ unsigned g_bar_count;
__device__ volatile unsigned g_bar_gen;

__device__ __forceinline__ float sigf(float x) {
    return 1.0f / (1.0f + __expf(-x));
}
__device__ __forceinline__ float tanhfast(float x) {
    x = fminf(fmaxf(x, -15.0f), 15.0f);
    float e = __expf(2.0f * x);
    return __fdividef(e - 1.0f, e + 1.0f);
}

__device__ __forceinline__ void cpa16(uint32_t saddr, const void* gptr) {
    asm volatile("cp.async.cg.shared.global [%0], [%1], 16;"
                 :: "r"(saddr), "l"(gptr));
}
#define CP_COMMIT() asm volatile("cp.async.commit_group;")
#define CP_WAIT(n)  asm volatile("cp.async.wait_group %0;" :: "n"(n))

// sm_90-baseline bulk async copy
__device__ __forceinline__ void bulk_copy(uint32_t dst_smem, const void* src,
                                          uint32_t bytes, uint32_t mbar) {
    asm volatile(
        "cp.async.bulk.shared::cta.global.mbarrier::complete_tx::bytes "
        "[%0], [%1], %2, [%3];"
        :: "r"(dst_smem), "l"(src), "r"(bytes), "r"(mbar) : "memory");
}
#define MBAR_INIT(mb) \
    asm volatile("mbarrier.init.shared.b64 [%0], 1;" :: "r"(mb) : "memory")
#define MBAR_EXPECT_TX(mb, bytes) \
    asm volatile("mbarrier.arrive.expect_tx.shared.b64 _, [%0], %1;" \
                 :: "r"(mb), "r"(bytes) : "memory")
__device__ __forceinline__ void mbar_wait(uint32_t mb, uint32_t parity) {
    asm volatile(
        "{\n\t.reg .pred P;\n"
        "L_%=:\n\t"
        "mbarrier.try_wait.parity.acquire.cta.shared::cta.b64 P, [%0], %1;\n\t"
        "@P bra D_%=;\n\tbra L_%=;\n"
        "D_%=:\n\t}" :: "r"(mb), "r"(parity) : "memory");
}

#define LDSM_X4(r0,r1,r2,r3,addr) \
    asm volatile("ldmatrix.sync.aligned.m8n8.x4.shared.b16 {%0,%1,%2,%3}, [%4];" \
        : "=r"(r0),"=r"(r1),"=r"(r2),"=r"(r3) : "r"(addr))
#define LDSM_X4T(r0,r1,r2,r3,addr) \
    asm volatile("ldmatrix.sync.aligned.m8n8.x4.trans.shared.b16 {%0,%1,%2,%3}, [%4];" \
        : "=r"(r0),"=r"(r1),"=r"(r2),"=r"(r3) : "r"(addr))
#define LDSM_X2T(r0,r1,addr) \
    asm volatile("ldmatrix.sync.aligned.m8n8.x2.trans.shared.b16 {%0,%1}, [%2];" \
        : "=r"(r0),"=r"(r1) : "r"(addr))
#define MMA16816(d0,d1,d2,d3,a0,a1,a2,a3,b0,b1) \
    asm volatile("mma.sync.aligned.m16n8k16.row.col.f32.bf16.bf16.f32 " \
        "{%0,%1,%2,%3}, {%4,%5,%6,%7}, {%8,%9}, {%0,%1,%2,%3};" \
        : "+f"(d0),"+f"(d1),"+f"(d2),"+f"(d3) \
        : "r"(a0),"r"(a1),"r"(a2),"r"(a3),"r"(b0),"r"(b1))

__device__ __forceinline__ void grid_sync() {
    __syncthreads();
    if (threadIdx.x == 0) {
        unsigned old = g_bar_gen;
        __threadfence();
        unsigned t = atomicAdd(&g_bar_count, 1u);
        if (t == REC_CTAS - 1) {
            atomicExch(&g_bar_count, 0u);
            __threadfence();
            g_bar_gen = old + 1u;
        } else {
            while (g_bar_gen == old) { }
            __threadfence();
        }
    }
    __syncthreads();
}

// ============================================================================
// Kernel P1: Whh -> split-bf16 rec tiles (M=32: R = gate*512+m*8+u, r=gate*8+u)
// ============================================================================
__global__ void prep_whh(const float* __restrict__ Whh) {
    int R = blockIdx.x;
    int gate = R >> 9, rem = R & 511;
    int m = rem >> 3, u = rem & 7;
    int r = gate * 8 + u;
    for (int k = threadIdx.x; k < HH; k += blockDim.x) {
        float w = Whh[(size_t)R * HH + k];
        __nv_bfloat16 hi = __float2bfloat16(w);
        __nv_bfloat16 lo = __float2bfloat16(w - __bfloat162float(hi));
        g_Abf[((size_t)(m * 2 + 0) * 32 + r) * HH + k] = hi;
        g_Abf[((size_t)(m * 2 + 1) * 32 + r) * HH + k] = lo;
    }
}

// ============================================================================
// Kernel P2: Wih -> split-bf16 [copy][R][k]
// ============================================================================
__global__ void prep_wih(const float* __restrict__ Wih) {
    int R = blockIdx.x;
    for (int k = threadIdx.x; k < II; k += blockDim.x) {
        float w = Wih[(size_t)R * II + k];
        __nv_bfloat16 hi = __float2bfloat16(w);
        __nv_bfloat16 lo = __float2bfloat16(w - __bfloat162float(hi));
        g_wihbf[(size_t)R * II + k] = hi;
        g_wihbf[(size_t)(2048 + R) * II + k] = lo;
    }
}

// ============================================================================
// Kernel P3: x[t] -> split-bf16 transposed [t][copy][k][b]
// ============================================================================
__global__ void prep_x(const float* __restrict__ x) {
    __shared__ float xs[64 * 257];
    const int t = blockIdx.x, tid = threadIdx.x;
    for (int idx = tid; idx < 64 * 64; idx += 256) {
        int b = idx >> 6, i = idx & 63;
        float4 v = *(const float4*)(x + ((size_t)t * BB + b) * II + i * 4);
        xs[b * 257 + i*4 + 0] = v.x; xs[b * 257 + i*4 + 1] = v.y;
        xs[b * 257 + i*4 + 2] = v.z; xs[b * 257 + i*4 + 3] = v.w;
    }
    __syncthreads();
    __nv_bfloat16* dst = g_xbf + (size_t)t * (2 * 256 * 64);
    for (int idx = tid; idx < 256 * 64; idx += 256) {
        int k = idx >> 6, b = idx & 63;
        float v = xs[b * 257 + k];
        __nv_bfloat16 hi = __float2bfloat16(v);
        __nv_bfloat16 lo = __float2bfloat16(v - __bfloat162float(hi));
        dst[(size_t)k * 64 + b] = hi;
        dst[(size_t)(256 + k) * 64 + b] = lo;
    }
}

// ============================================================================
// Kernel 1: pregemm via HMMA (unchanged from R11/R13)
// ============================================================================
#define PG_ACOPY 18432
#define PG_AOFF  0
#define PG_BOFF  36864
#define PG_BCOPY 9216
#define PG_CHUNK 55296
#define PG_BIAS  (2 * PG_CHUNK)
#define PG_SMEM  (PG_BIAS + 512 + 256)

__device__ __forceinline__ void pg_stage(uint32_t sb, int buf, int mbG, int t,
                                         int kc, int tid) {
    uint32_t dst = sb + buf * PG_CHUNK;
    #pragma unroll
    for (int j = 0; j < 8; j++) {
        int idx = j * 256 + tid;
        int c2 = idx >> 10, rem = idx & 1023;
        int r = rem >> 3, i = rem & 7;
        cpa16(dst + PG_AOFF + c2 * PG_ACOPY + r * 144 + i * 16,
              g_wihbf + ((size_t)(c2 * 2048 + mbG * 128 + r)) * II + kc * 64 + i * 8);
    }
    #pragma unroll
    for (int j = 0; j < 4; j++) {
        int idx = j * 256 + tid;
        int c2 = idx >> 9, rem = idx & 511;
        int k = rem >> 3, i = rem & 7;
        cpa16(dst + PG_BOFF + c2 * PG_BCOPY + k * 144 + i * 16,
              g_xbf + ((size_t)t * 2 + c2) * (256 * 64) + (size_t)(kc * 64 + k) * 64 + i * 8);
    }
    CP_COMMIT();
}

__global__ void __launch_bounds__(256, 1) pregemm_mma(
    const float* __restrict__ bih, const float* __restrict__ bhh)
{
    extern __shared__ char smraw[];
    uint32_t sb0 = (uint32_t)__cvta_generic_to_shared(smraw);
    uint32_t sb  = (sb0 + 127u) & ~127u;
    char* smem = smraw + (sb - sb0);
    float* bsm = (float*)(smem + PG_BIAS);

    const int t   = blockIdx.x >> 4;
    const int mbG = blockIdx.x & 15;
    const int tid = threadIdx.x;
    const int wid = tid >> 5;
    const int lane = tid & 31;

    if (tid < 128) {
        int R = mbG * 128 + tid;
        bsm[tid] = bih[R] + bhh[R];
    }

    pg_stage(sb, 0, mbG, t, 0, tid);
    pg_stage(sb, 1, mbG, t, 1, tid);

    float d[8][4];
    #pragma unroll
    for (int i = 0; i < 8; i++)
        #pragma unroll
        for (int j = 0; j < 4; j++) d[i][j] = 0.0f;

    const uint32_t aRel = (uint32_t)(lane & 15) * 144 + (uint32_t)(lane >> 4) * 16;
    const uint32_t bRel = (uint32_t)(lane & 15) * 144 + (uint32_t)wid * 16;

    #pragma unroll
    for (int c = 0; c < 4; c++) {
        if (c < 3) CP_WAIT(1); else CP_WAIT(0);
        __syncthreads();
        uint32_t buf = sb + (c & 1) * PG_CHUNK;
        uint32_t aB = buf + PG_AOFF + aRel;
        uint32_t bB = buf + PG_BOFF + bRel;
        #pragma unroll
        for (int ks = 0; ks < 4; ks++) {
            uint32_t bh0, bh1, bl0, bl1;
            LDSM_X2T(bh0, bh1, bB + ks * 2304);
            LDSM_X2T(bl0, bl1, bB + PG_BCOPY + ks * 2304);
            #pragma unroll
            for (int mb = 0; mb < 8; mb++) {
                uint32_t ah0,ah1,ah2,ah3, al0,al1,al2,al3;
                LDSM_X4(ah0,ah1,ah2,ah3, aB + mb * (16*144) + ks * 32);
                LDSM_X4(al0,al1,al2,al3, aB + PG_ACOPY + mb * (16*144) + ks * 32);
                MMA16816(d[mb][0],d[mb][1],d[mb][2],d[mb][3], ah0,ah1,ah2,ah3, bh0,bh1);
                MMA16816(d[mb][0],d[mb][1],d[mb][2],d[mb][3], ah0,ah1,ah2,ah3, bl0,bl1);
                MMA16816(d[mb][0],d[mb][1],d[mb][2],d[mb][3], al0,al1,al2,al3, bh0,bh1);
            }
        }
        __syncthreads();
        if (c < 2) pg_stage(sb, c & 1, mbG, t, c + 2, tid);
    }

    float* outp = g_xgT + (size_t)t * (G4 * BB);
    const int c0 = wid * 8 + (lane & 3) * 2;
    #pragma unroll
    for (int mb = 0; mb < 8; mb++) {
        int r0 = mb * 16 + (lane >> 2);
        int R0 = mbG * 128 + r0;
        float b0 = bsm[r0], b1 = bsm[r0 + 8];
        *(float2*)(outp + (size_t)R0 * BB + c0) =
            make_float2(d[mb][0] + b0, d[mb][1] + b0);
        *(float2*)(outp + (size_t)(R0 + 8) * BB + c0) =
            make_float2(d[mb][2] + b1, d[mb][3] + b1);
    }
}

// ============================================================================
// Kernel 2: persistent HMMA recurrence, bulk-copy staging, 64 CTAs x M=32.
// Warp (mw = wid>>2, nw = wid&3): tile M[16mw,16mw+16) x N[16nw,16nw+16).
// Per step: 2 bulk copies (72KB hi, 72KB lo); pass1 (hi B) overlaps lo xfer.
// ============================================================================
#define HSM_OFF   0
#define HSM_PLANE 73728           // 512 rows * 144B
#define ASM_OFF   147456
#define ASM_COPY  33280           // 32 rows * 1040B
#define GSM_OFF   214016
#define GSM_STR   66
#define CSM_OFF   222464          // 32*66*4 = 8448
#define MBAR_OFF  224512          // csm 8*64*4 = 2048
#define REC_SMEM  (224640 + 256)

__global__ void __launch_bounds__(256, 1) lstm_rec_mma(
    float* __restrict__ d_out, int out_size)
{
    extern __shared__ char smraw[];
    uint32_t sb0 = (uint32_t)__cvta_generic_to_shared(smraw);
    uint32_t sb  = (sb0 + 127u) & ~127u;
    char* smem = smraw + (sb - sb0);

    float* gsm = (float*)(smem + GSM_OFF);
    float* csm = (float*)(smem + CSM_OFF);
    const uint32_t mb0 = sb + MBAR_OFF, mb1 = sb + MBAR_OFF + 8;

    const int m    = blockIdx.x;
    const int tid  = threadIdx.x;
    const int wid  = tid >> 5;
    const int lane = tid & 31;
    const int mw   = wid >> 2;
    const int nw   = wid & 3;
    const int b    = tid & 63;
    const int u0   = tid >> 6;      // units u0 and u0+4

    // one-time: A tiles -> smem (both copies), 1040B row stride
    for (int idx = tid; idx < 2 * 32 * 64; idx += 256) {
        int c = idx >> 11, rem = idx & 2047;
        int r = rem >> 6, i = rem & 63;
        uint4 v = *(const uint4*)(g_Abf + ((size_t)(m*2+c)*32 + r) * HH + i*8);
        *(uint4*)(smem + ASM_OFF + c*ASM_COPY + r*1040 + i*16) = v;
    }
    // zero padded h ping-pong: 2*2*512*72 bf16 = 36864 uint4
    for (int i = m * 256 + tid; i < 36864; i += REC_CTAS * 256)
        ((uint4*)g_hbf)[i] = make_uint4(0, 0, 0, 0);
    csm[u0 * 64 + b] = 0.0f;
    csm[(u0 + 4) * 64 + b] = 0.0f;
    if (tid == 0) { MBAR_INIT(mb0); MBAR_INIT(mb1); }
    __threadfence();
    grid_sync();

    const uint32_t aBase = sb + ASM_OFF
                         + (uint32_t)(mw * 16 + (lane & 15)) * 1040
                         + (uint32_t)(lane >> 4) * 16;
    const uint32_t bBase = sb + HSM_OFF + (uint32_t)(lane & 15) * 144
                         + (uint32_t)(nw * 32) + (uint32_t)(lane >> 4) * 16;

    int cur = 0;
    for (int step = 0; step < TT; step++) {
        const __nv_bfloat16* hsrc = g_hbf + (size_t)cur * (2 * 512 * 72);
        if (tid == 0) {
            MBAR_EXPECT_TX(mb0, HSM_PLANE);
            bulk_copy(sb + HSM_OFF, hsrc, HSM_PLANE, mb0);
            MBAR_EXPECT_TX(mb1, HSM_PLANE);
            bulk_copy(sb + HSM_OFF + HSM_PLANE, hsrc + 512 * 72, HSM_PLANE, mb1);
        }

        // prefetch xg (2 units x 4 gates)
        const float* xgs = g_xgT + (size_t)step * (G4 * BB);
        float xg[2][4];
        #pragma unroll
        for (int i = 0; i < 2; i++) {
            int gu = m * 8 + u0 + i * 4;
            #pragma unroll
            for (int g = 0; g < 4; g++)
                xg[i][g] = __ldcs(xgs + (size_t)(g * HH + gu) * BB + b);
        }

        float d0[4] = {0.f,0.f,0.f,0.f};
        float d1[4] = {0.f,0.f,0.f,0.f};

        // pass 1: hi B plane (whi*hhi + wlo*hhi)
        mbar_wait(mb0, step & 1);
        #pragma unroll 8
        for (int ks = 0; ks < 32; ks++) {
            uint32_t ah0,ah1,ah2,ah3, al0,al1,al2,al3;
            uint32_t bh0,bh1,bh2,bh3;
            LDSM_X4(ah0,ah1,ah2,ah3, aBase + ks*32);
            LDSM_X4(al0,al1,al2,al3, aBase + ASM_COPY + ks*32);
            LDSM_X4T(bh0,bh1,bh2,bh3, bBase + ks*2304);
            MMA16816(d0[0],d0[1],d0[2],d0[3], ah0,ah1,ah2,ah3, bh0,bh1);
            MMA16816(d0[0],d0[1],d0[2],d0[3], al0,al1,al2,al3, bh0,bh1);
            MMA16816(d1[0],d1[1],d1[2],d1[3], ah0,ah1,ah2,ah3, bh2,bh3);
            MMA16816(d1[0],d1[1],d1[2],d1[3], al0,al1,al2,al3, bh2,bh3);
        }
        // pass 2: lo B plane (whi*hlo)
        mbar_wait(mb1, step & 1);
        #pragma unroll 8
        for (int ks = 0; ks < 32; ks++) {
            uint32_t ah0,ah1,ah2,ah3, bl0,bl1,bl2,bl3;
            LDSM_X4(ah0,ah1,ah2,ah3, aBase + ks*32);
            LDSM_X4T(bl0,bl1,bl2,bl3, bBase + HSM_PLANE + ks*2304);
            MMA16816(d0[0],d0[1],d0[2],d0[3], ah0,ah1,ah2,ah3, bl0,bl1);
            MMA16816(d1[0],d1[1],d1[2],d1[3], ah0,ah1,ah2,ah3, bl2,bl3);
        }

        {
            int r0 = mw * 16 + (lane >> 2);
            int c0 = nw * 16 + (lane & 3) * 2;
            *(float2*)&gsm[r0 * GSM_STR + c0]           = make_float2(d0[0], d0[1]);
            *(float2*)&gsm[(r0 + 8) * GSM_STR + c0]     = make_float2(d0[2], d0[3]);
            *(float2*)&gsm[r0 * GSM_STR + c0 + 8]       = make_float2(d1[0], d1[1]);
            *(float2*)&gsm[(r0 + 8) * GSM_STR + c0 + 8] = make_float2(d1[2], d1[3]);
        }
        __syncthreads();

        // cell update: thread handles units u0 and u0+4 at batch b
        #pragma unroll
        for (int i = 0; i < 2; i++) {
            int ul = u0 + i * 4;
            int gu = m * 8 + ul;
            float p0 = gsm[(0*8 + ul) * GSM_STR + b] + xg[i][0];
            float p1 = gsm[(1*8 + ul) * GSM_STR + b] + xg[i][1];
            float p2 = gsm[(2*8 + ul) * GSM_STR + b] + xg[i][2];
            float p3 = gsm[(3*8 + ul) * GSM_STR + b] + xg[i][3];
            float ig = sigf(p0), fg = sigf(p1);
            float gg = tanhfast(p2), og = sigf(p3);
            float c  = fmaf(fg, csm[ul * 64 + b], ig * gg);
            float h  = og * tanhfast(c);
            csm[ul * 64 + b] = c;
            __stcs(&g_hsT[(size_t)step * (HH*BB) + (size_t)gu * BB + b], h);
            __nv_bfloat16 hh = __float2bfloat16(h);
            __nv_bfloat16 hl = __float2bfloat16(h - __bfloat162float(hh));
            int nxt = cur ^ 1;
            __nv_bfloat16* hw = g_hbf + (size_t)nxt * (2 * 512 * 72);
            hw[(size_t)gu * 72 + b] = hh;                     // hi plane
            hw[(size_t)(512 + gu) * 72 + b] = hl;             // lo plane
            if (step == TT - 1 && out_size >= TT*BB*OO + 2*BB*HH) {
                d_out[TT*BB*OO + (size_t)b * HH + gu] = h;
                d_out[TT*BB*OO + BB*HH + (size_t)b * HH + gu] = c;
            }
        }
        __threadfence();
        grid_sync();
        cur ^= 1;
    }
}

// ============================================================================
// Kernel 3: FC epilogue
// ============================================================================
__global__ void __launch_bounds__(320) fc_kernel(
    const float* __restrict__ fcw, const float* __restrict__ fcb,
    float* __restrict__ out)
{
    __shared__ float wsm[OO][HH];
    __shared__ float bsm[OO];
    const int t = blockIdx.x, tid = threadIdx.x;
    for (int s = tid; s < OO * HH; s += 320) wsm[s / HH][s % HH] = fcw[s];
    if (tid < OO) bsm[tid] = fcb[tid];
    __syncthreads();
    const int o = tid >> 6, b = tid & 63;
    const float* hp = g_hsT + (size_t)t * (HH * BB) + b;
    float acc = bsm[o];
    #pragma unroll 8
    for (int k = 0; k < HH; k++)
        acc = fmaf(__ldcs(hp + (size_t)k * BB), wsm[o][k], acc);
    out[(size_t)t * (BB * OO) + b * OO + o] = acc;
}

// ============================================================================
extern "C" void kernel_launch(void* const* d_in, const int* in_sizes, int n_in,
                              void* d_out, int out_size) {
    const float* x   = (const float*)d_in[0];
    const float* Wih = (const float*)d_in[1];
    const float* Whh = (const float*)d_in[2];
    const float* bih = (const float*)d_in[3];
    const float* bhh = (const float*)d_in[4];
    const float* fcw = (const float*)d_in[5];
    const float* fcb = (const float*)d_in[6];
    float* out = (float*)d_out;

    cudaFuncSetAttribute(lstm_rec_mma,
                         cudaFuncAttributeMaxDynamicSharedMemorySize, REC_SMEM);
    cudaFuncSetAttribute(pregemm_mma,
                         cudaFuncAttributeMaxDynamicSharedMemorySize, PG_SMEM);

    prep_whh<<<G4, 128>>>(Whh);
    prep_wih<<<G4, 128>>>(Wih);
    prep_x<<<TT, 256>>>(x);
    pregemm_mma<<<TT * 16, 256, PG_SMEM>>>(bih, bhh);
    lstm_rec_mma<<<REC_CTAS, 256, REC_SMEM>>>(out, out_size);
    fc_kernel<<<TT, 320>>>(fcw, fcb, out);
}

// round 15
// speedup vs baseline: 1.2513x; 1.2513x over previous
#include <cuda_runtime.h>
#include <cuda_bf16.h>
#include <cuda_fp16.h>
#include <math.h>
#include <stdint.h>

// LSTM: T=1024, B=64, I=256, H=512, O=5
// out = [outputs (T*B*O) | h_T (B*H) | c_T (B*H)]

#define TT 1024
#define BB 64
#define II 256
#define HH 512
#define G4 2048
#define OO 5
#define REC_CTAS 128

// ---- device scratch ----
__device__ float g_xgT[(size_t)TT * G4 * BB];     // [T][4H][B]
__device__ float g_hsT[(size_t)TT * HH * BB];     // [T][H][B]
// Whh split-fp16 per rec-CTA tile: [(m*2+copy)*16 + r][512], r = gate*4+u
__device__ __half g_Awhh[128 * 2 * 16 * 512];
// h fp16 single plane, PADDED ldmatrix-ready, ping-pong: [pp 2][k 512][72]
__device__ __align__(16) __half g_hf16[2 * 512 * 72];
// Wih split-bf16: [copy 2][R 2048][k 256]  (pregemm unchanged)
__device__ __nv_bfloat16 g_wihbf[2 * 2048 * 256];
// x split-bf16, transposed per t: [t 1024][copy 2][k 256][b 64]
__device__ __nv_bfloat16 g_xbf[(size_t)1024 * 2 * 256 * 64];
__device__ unsigned g_bar_count;
__device__ volatile unsigned g_bar_gen;

__device__ __forceinline__ float sigf(float x) {
    return 1.0f / (1.0f + __expf(-x));
}
__device__ __forceinline__ float tanhfast(float x) {
    x = fminf(fmaxf(x, -15.0f), 15.0f);
    float e = __expf(2.0f * x);
    return __fdividef(e - 1.0f, e + 1.0f);
}

__device__ __forceinline__ void cpa16(uint32_t saddr, const void* gptr) {
    asm volatile("cp.async.cg.shared.global [%0], [%1], 16;"
                 :: "r"(saddr), "l"(gptr));
}
#define CP_COMMIT() asm volatile("cp.async.commit_group;")
#define CP_WAIT(n)  asm volatile("cp.async.wait_group %0;" :: "n"(n))

__device__ __forceinline__ void bulk_copy(uint32_t dst_smem, const void* src,
                                          uint32_t bytes, uint32_t mbar) {
    asm volatile(
        "cp.async.bulk.shared::cta.global.mbarrier::complete_tx::bytes "
        "[%0], [%1], %2, [%3];"
        :: "r"(dst_smem), "l"(src), "r"(bytes), "r"(mbar) : "memory");
}
#define MBAR_INIT(mb) \
    asm volatile("mbarrier.init.shared.b64 [%0], 1;" :: "r"(mb) : "memory")
#define MBAR_EXPECT_TX(mb, bytes) \
    asm volatile("mbarrier.arrive.expect_tx.shared.b64 _, [%0], %1;" \
                 :: "r"(mb), "r"(bytes) : "memory")
__device__ __forceinline__ void mbar_wait(uint32_t mb, uint32_t parity) {
    asm volatile(
        "{\n\t.reg .pred P;\n"
        "L_%=:\n\t"
        "mbarrier.try_wait.parity.acquire.cta.shared::cta.b64 P, [%0], %1;\n\t"
        "@P bra D_%=;\n\tbra L_%=;\n"
        "D_%=:\n\t}" :: "r"(mb), "r"(parity) : "memory");
}

#define LDSM_X4(r0,r1,r2,r3,addr) \
    asm volatile("ldmatrix.sync.aligned.m8n8.x4.shared.b16 {%0,%1,%2,%3}, [%4];" \
        : "=r"(r0),"=r"(r1),"=r"(r2),"=r"(r3) : "r"(addr))
#define LDSM_X2T(r0,r1,addr) \
    asm volatile("ldmatrix.sync.aligned.m8n8.x2.trans.shared.b16 {%0,%1}, [%2];" \
        : "=r"(r0),"=r"(r1) : "r"(addr))
// bf16 MMA (pregemm)
#define MMA16816(d0,d1,d2,d3,a0,a1,a2,a3,b0,b1) \
    asm volatile("mma.sync.aligned.m16n8k16.row.col.f32.bf16.bf16.f32 " \
        "{%0,%1,%2,%3}, {%4,%5,%6,%7}, {%8,%9}, {%0,%1,%2,%3};" \
        : "+f"(d0),"+f"(d1),"+f"(d2),"+f"(d3) \
        : "r"(a0),"r"(a1),"r"(a2),"r"(a3),"r"(b0),"r"(b1))
// fp16 MMA (recurrence)
#define MMAH16816(d0,d1,d2,d3,a0,a1,a2,a3,b0,b1) \
    asm volatile("mma.sync.aligned.m16n8k16.row.col.f32.f16.f16.f32 " \
        "{%0,%1,%2,%3}, {%4,%5,%6,%7}, {%8,%9}, {%0,%1,%2,%3};" \
        : "+f"(d0),"+f"(d1),"+f"(d2),"+f"(d3) \
        : "r"(a0),"r"(a1),"r"(a2),"r"(a3),"r"(b0),"r"(b1))

__device__ __forceinline__ void grid_sync() {
    __syncthreads();
    if (threadIdx.x == 0) {
        unsigned old = g_bar_gen;
        __threadfence();
        unsigned t = atomicAdd(&g_bar_count, 1u);
        if (t == REC_CTAS - 1) {
            atomicExch(&g_bar_count, 0u);
            __threadfence();
            g_bar_gen = old + 1u;
        } else {
            while (g_bar_gen == old) { }
            __threadfence();
        }
    }
    __syncthreads();
}

// ============================================================================
// Kernel P1: Whh -> split-fp16 rec tiles (R = gate*512 + m*4 + u)
// w in [-0.044, 0.044] -> fp16 exact to 2^-11 rel; hi+lo to 2^-22.
// ============================================================================
__global__ void prep_whh(const float* __restrict__ Whh) {
    int R = blockIdx.x;
    int gate = R >> 9, rem = R & 511;
    int m = rem >> 2, u = rem & 3;
    int r = gate * 4 + u;
    for (int k = threadIdx.x; k < HH; k += blockDim.x) {
        float w = Whh[(size_t)R * HH + k];
        __half hi = __float2half(w);
        __half lo = __float2half(w - __half2float(hi));
        g_Awhh[((size_t)(m * 2 + 0) * 16 + r) * HH + k] = hi;
        g_Awhh[((size_t)(m * 2 + 1) * 16 + r) * HH + k] = lo;
    }
}

// ============================================================================
// Kernel P2: Wih -> split-bf16 [copy][R][k] (pregemm path, unchanged)
// ============================================================================
__global__ void prep_wih(const float* __restrict__ Wih) {
    int R = blockIdx.x;
    for (int k = threadIdx.x; k < II; k += blockDim.x) {
        float w = Wih[(size_t)R * II + k];
        __nv_bfloat16 hi = __float2bfloat16(w);
        __nv_bfloat16 lo = __float2bfloat16(w - __bfloat162float(hi));
        g_wihbf[(size_t)R * II + k] = hi;
        g_wihbf[(size_t)(2048 + R) * II + k] = lo;
    }
}

// ============================================================================
// Kernel P3: x[t] -> split-bf16 transposed [t][copy][k][b]
// ============================================================================
__global__ void prep_x(const float* __restrict__ x) {
    __shared__ float xs[64 * 257];
    const int t = blockIdx.x, tid = threadIdx.x;
    for (int idx = tid; idx < 64 * 64; idx += 256) {
        int b = idx >> 6, i = idx & 63;
        float4 v = *(const float4*)(x + ((size_t)t * BB + b) * II + i * 4);
        xs[b * 257 + i*4 + 0] = v.x; xs[b * 257 + i*4 + 1] = v.y;
        xs[b * 257 + i*4 + 2] = v.z; xs[b * 257 + i*4 + 3] = v.w;
    }
    __syncthreads();
    __nv_bfloat16* dst = g_xbf + (size_t)t * (2 * 256 * 64);
    for (int idx = tid; idx < 256 * 64; idx += 256) {
        int k = idx >> 6, b = idx & 63;
        float v = xs[b * 257 + k];
        __nv_bfloat16 hi = __float2bfloat16(v);
        __nv_bfloat16 lo = __float2bfloat16(v - __bfloat162float(hi));
        dst[(size_t)k * 64 + b] = hi;
        dst[(size_t)(256 + k) * 64 + b] = lo;
    }
}

// ============================================================================
// Kernel 1: pregemm via HMMA (unchanged from R11/R13)
// ============================================================================
#define PG_ACOPY 18432
#define PG_AOFF  0
#define PG_BOFF  36864
#define PG_BCOPY 9216
#define PG_CHUNK 55296
#define PG_BIAS  (2 * PG_CHUNK)
#define PG_SMEM  (PG_BIAS + 512 + 256)

__device__ __forceinline__ void pg_stage(uint32_t sb, int buf, int mbG, int t,
                                         int kc, int tid) {
    uint32_t dst = sb + buf * PG_CHUNK;
    #pragma unroll
    for (int j = 0; j < 8; j++) {
        int idx = j * 256 + tid;
        int c2 = idx >> 10, rem = idx & 1023;
        int r = rem >> 3, i = rem & 7;
        cpa16(dst + PG_AOFF + c2 * PG_ACOPY + r * 144 + i * 16,
              g_wihbf + ((size_t)(c2 * 2048 + mbG * 128 + r)) * II + kc * 64 + i * 8);
    }
    #pragma unroll
    for (int j = 0; j < 4; j++) {
        int idx = j * 256 + tid;
        int c2 = idx >> 9, rem = idx & 511;
        int k = rem >> 3, i = rem & 7;
        cpa16(dst + PG_BOFF + c2 * PG_BCOPY + k * 144 + i * 16,
              g_xbf + ((size_t)t * 2 + c2) * (256 * 64) + (size_t)(kc * 64 + k) * 64 + i * 8);
    }
    CP_COMMIT();
}

__global__ void __launch_bounds__(256, 1) pregemm_mma(
    const float* __restrict__ bih, const float* __restrict__ bhh)
{
    extern __shared__ char smraw[];
    uint32_t sb0 = (uint32_t)__cvta_generic_to_shared(smraw);
    uint32_t sb  = (sb0 + 127u) & ~127u;
    char* smem = smraw + (sb - sb0);
    float* bsm = (float*)(smem + PG_BIAS);

    const int t   = blockIdx.x >> 4;
    const int mbG = blockIdx.x & 15;
    const int tid = threadIdx.x;
    const int wid = tid >> 5;
    const int lane = tid & 31;

    if (tid < 128) {
        int R = mbG * 128 + tid;
        bsm[tid] = bih[R] + bhh[R];
    }

    pg_stage(sb, 0, mbG, t, 0, tid);
    pg_stage(sb, 1, mbG, t, 1, tid);

    float d[8][4];
    #pragma unroll
    for (int i = 0; i < 8; i++)
        #pragma unroll
        for (int j = 0; j < 4; j++) d[i][j] = 0.0f;

    const uint32_t aRel = (uint32_t)(lane & 15) * 144 + (uint32_t)(lane >> 4) * 16;
    const uint32_t bRel = (uint32_t)(lane & 15) * 144 + (uint32_t)wid * 16;

    #pragma unroll
    for (int c = 0; c < 4; c++) {
        if (c < 3) CP_WAIT(1); else CP_WAIT(0);
        __syncthreads();
        uint32_t buf = sb + (c & 1) * PG_CHUNK;
        uint32_t aB = buf + PG_AOFF + aRel;
        uint32_t bB = buf + PG_BOFF + bRel;
        #pragma unroll
        for (int ks = 0; ks < 4; ks++) {
            uint32_t bh0, bh1, bl0, bl1;
            LDSM_X2T(bh0, bh1, bB + ks * 2304);
            LDSM_X2T(bl0, bl1, bB + PG_BCOPY + ks * 2304);
            #pragma unroll
            for (int mb = 0; mb < 8; mb++) {
                uint32_t ah0,ah1,ah2,ah3, al0,al1,al2,al3;
                LDSM_X4(ah0,ah1,ah2,ah3, aB + mb * (16*144) + ks * 32);
                LDSM_X4(al0,al1,al2,al3, aB + PG_ACOPY + mb * (16*144) + ks * 32);
                MMA16816(d[mb][0],d[mb][1],d[mb][2],d[mb][3], ah0,ah1,ah2,ah3, bh0,bh1);
                MMA16816(d[mb][0],d[mb][1],d[mb][2],d[mb][3], ah0,ah1,ah2,ah3, bl0,bl1);
                MMA16816(d[mb][0],d[mb][1],d[mb][2],d[mb][3], al0,al1,al2,al3, bh0,bh1);
            }
        }
        __syncthreads();
        if (c < 2) pg_stage(sb, c & 1, mbG, t, c + 2, tid);
    }

    float* outp = g_xgT + (size_t)t * (G4 * BB);
    const int c0 = wid * 8 + (lane & 3) * 2;
    #pragma unroll
    for (int mb = 0; mb < 8; mb++) {
        int r0 = mb * 16 + (lane >> 2);
        int R0 = mbG * 128 + r0;
        float b0 = bsm[r0], b1 = bsm[r0 + 8];
        *(float2*)(outp + (size_t)R0 * BB + c0) =
            make_float2(d[mb][0] + b0, d[mb][1] + b0);
        *(float2*)(outp + (size_t)(R0 + 8) * BB + c0) =
            make_float2(d[mb][2] + b1, d[mb][3] + b1);
    }
}

// ============================================================================
// Kernel 2: persistent fp16-HMMA recurrence, 128 CTAs x M=16.
// h = SINGLE fp16 plane (72KB/step), staged as 2x36KB chunks on 2 mbarriers.
// w = fp16 hi/lo in smem. 2 MMA terms: whi*h + wlo*h.
// ============================================================================
#define HSM_OFF   0
#define HSM_PLANE 73728           // 512 rows * 144B
#define HSM_HALF  36864           // 256 rows
#define ASM_OFF   73728
#define ASM_COPY  16640           // 16 rows * 1040B
#define GSM_OFF   107008
#define GSM_STR   66
#define CSM_OFF   111232          // gsm 16*66*4 = 4224
#define MBAR_OFF  112256          // csm 4*64*4 = 1024
#define REC_SMEM  (112384 + 256)

__global__ void __launch_bounds__(256, 1) lstm_rec_mma(
    float* __restrict__ d_out, int out_size)
{
    extern __shared__ char smraw[];
    uint32_t sb0 = (uint32_t)__cvta_generic_to_shared(smraw);
    uint32_t sb  = (sb0 + 127u) & ~127u;
    char* smem = smraw + (sb - sb0);

    float* gsm = (float*)(smem + GSM_OFF);
    float* csm = (float*)(smem + CSM_OFF);
    const uint32_t mb0 = sb + MBAR_OFF, mb1 = sb + MBAR_OFF + 8;

    const int m    = blockIdx.x;
    const int tid  = threadIdx.x;
    const int wid  = tid >> 5;
    const int lane = tid & 31;
    const int b    = tid & 63;
    const int u    = tid >> 6;

    // one-time: A tiles (fp16 hi/lo) -> smem, 1040B row stride
    for (int idx = tid; idx < 2 * 16 * 64; idx += 256) {
        int c = idx >> 10, rem = idx & 1023;
        int r = rem >> 6, i = rem & 63;
        uint4 v = *(const uint4*)(g_Awhh + ((size_t)(m*2+c)*16 + r) * HH + i*8);
        *(uint4*)(smem + ASM_OFF + c*ASM_COPY + r*1040 + i*16) = v;
    }
    // zero fp16 h ping-pong: 2*512*72 halves = 9216 uint4
    for (int i = m * 256 + tid; i < 9216; i += REC_CTAS * 256)
        ((uint4*)g_hf16)[i] = make_uint4(0, 0, 0, 0);
    csm[u * 64 + b] = 0.0f;
    if (tid == 0) { MBAR_INIT(mb0); MBAR_INIT(mb1); }
    __threadfence();
    grid_sync();

    const uint32_t aBase = sb + ASM_OFF + (uint32_t)(lane & 15) * 1040
                         + (uint32_t)(lane >> 4) * 16;
    const uint32_t bBase = sb + HSM_OFF + (uint32_t)(lane & 15) * 144
                         + (uint32_t)wid * 16;

    int cur = 0;
    for (int step = 0; step < TT; step++) {
        const __half* hsrc = g_hf16 + (size_t)cur * (512 * 72);
        if (tid == 0) {
            MBAR_EXPECT_TX(mb0, HSM_HALF);
            bulk_copy(sb + HSM_OFF, hsrc, HSM_HALF, mb0);
            MBAR_EXPECT_TX(mb1, HSM_HALF);
            bulk_copy(sb + HSM_OFF + HSM_HALF, hsrc + 256 * 72, HSM_HALF, mb1);
        }

        const float* xgs = g_xgT + (size_t)step * (G4 * BB);
        int gu = m * 4 + u;
        float xg0 = __ldcs(xgs + (size_t)(0*HH + gu) * BB + b);
        float xg1 = __ldcs(xgs + (size_t)(1*HH + gu) * BB + b);
        float xg2 = __ldcs(xgs + (size_t)(2*HH + gu) * BB + b);
        float xg3 = __ldcs(xgs + (size_t)(3*HH + gu) * BB + b);

        float d0 = 0.f, d1 = 0.f, d2 = 0.f, d3 = 0.f;

        // chunk 0: k in [0,256)
        mbar_wait(mb0, step & 1);
        #pragma unroll 8
        for (int ks = 0; ks < 16; ks++) {
            uint32_t ah0,ah1,ah2,ah3, al0,al1,al2,al3, bh0,bh1;
            LDSM_X4(ah0,ah1,ah2,ah3, aBase + ks*32);
            LDSM_X4(al0,al1,al2,al3, aBase + ASM_COPY + ks*32);
            LDSM_X2T(bh0,bh1, bBase + ks*2304);
            MMAH16816(d0,d1,d2,d3, ah0,ah1,ah2,ah3, bh0,bh1);
            MMAH16816(d0,d1,d2,d3, al0,al1,al2,al3, bh0,bh1);
        }
        // chunk 1: k in [256,512)
        mbar_wait(mb1, step & 1);
        #pragma unroll 8
        for (int ks = 16; ks < 32; ks++) {
            uint32_t ah0,ah1,ah2,ah3, al0,al1,al2,al3, bh0,bh1;
            LDSM_X4(ah0,ah1,ah2,ah3, aBase + ks*32);
            LDSM_X4(al0,al1,al2,al3, aBase + ASM_COPY + ks*32);
            LDSM_X2T(bh0,bh1, bBase + ks*2304);
            MMAH16816(d0,d1,d2,d3, ah0,ah1,ah2,ah3, bh0,bh1);
            MMAH16816(d0,d1,d2,d3, al0,al1,al2,al3, bh0,bh1);
        }

        {
            int r0 = lane >> 2;
            int cB = wid * 8 + (lane & 3) * 2;
            *(float2*)&gsm[r0 * GSM_STR + cB]       = make_float2(d0, d1);
            *(float2*)&gsm[(r0 + 8) * GSM_STR + cB] = make_float2(d2, d3);
        }
        __syncthreads();

        {
            float p0 = gsm[(0*4 + u) * GSM_STR + b] + xg0;
            float p1 = gsm[(1*4 + u) * GSM_STR + b] + xg1;
            float p2 = gsm[(2*4 + u) * GSM_STR + b] + xg2;
            float p3 = gsm[(3*4 + u) * GSM_STR + b] + xg3;
            float ig = sigf(p0), fg = sigf(p1);
            float gg = tanhfast(p2), og = sigf(p3);
            float c  = fmaf(fg, csm[u * 64 + b], ig * gg);
            float h  = og * tanhfast(c);
            csm[u * 64 + b] = c;
            __stcs(&g_hsT[(size_t)step * (HH*BB) + (size_t)gu * BB + b], h);
            int nxt = cur ^ 1;
            __half* hw = g_hf16 + (size_t)nxt * (512 * 72);
            hw[(size_t)gu * 72 + b] = __float2half(h);
            if (step == TT - 1 && out_size >= TT*BB*OO + 2*BB*HH) {
                d_out[TT*BB*OO + (size_t)b * HH + gu] = h;
                d_out[TT*BB*OO + BB*HH + (size_t)b * HH + gu] = c;
            }
        }
        __threadfence();
        grid_sync();
        cur ^= 1;
    }
}

// ============================================================================
// Kernel 3: FC epilogue
// ============================================================================
__global__ void __launch_bounds__(320) fc_kernel(
    const float* __restrict__ fcw, const float* __restrict__ fcb,
    float* __restrict__ out)
{
    __shared__ float wsm[OO][HH];
    __shared__ float bsm[OO];
    const int t = blockIdx.x, tid = threadIdx.x;
    for (int s = tid; s < OO * HH; s += 320) wsm[s / HH][s % HH] = fcw[s];
    if (tid < OO) bsm[tid] = fcb[tid];
    __syncthreads();
    const int o = tid >> 6, b = tid & 63;
    const float* hp = g_hsT + (size_t)t * (HH * BB) + b;
    float acc = bsm[o];
    #pragma unroll 8
    for (int k = 0; k < HH; k++)
        acc = fmaf(__ldcs(hp + (size_t)k * BB), wsm[o][k], acc);
    out[(size_t)t * (BB * OO) + b * OO + o] = acc;
}

// ============================================================================
extern "C" void kernel_launch(void* const* d_in, const int* in_sizes, int n_in,
                              void* d_out, int out_size) {
    const float* x   = (const float*)d_in[0];
    const float* Wih = (const float*)d_in[1];
    const float* Whh = (const float*)d_in[2];
    const float* bih = (const float*)d_in[3];
    const float* bhh = (const float*)d_in[4];
    const float* fcw = (const float*)d_in[5];
    const float* fcb = (const float*)d_in[6];
    float* out = (float*)d_out;

    cudaFuncSetAttribute(lstm_rec_mma,
                         cudaFuncAttributeMaxDynamicSharedMemorySize, REC_SMEM);
    cudaFuncSetAttribute(pregemm_mma,
                         cudaFuncAttributeMaxDynamicSharedMemorySize, PG_SMEM);

    prep_whh<<<G4, 128>>>(Whh);
    prep_wih<<<G4, 128>>>(Wih);
    prep_x<<<TT, 256>>>(x);
    pregemm_mma<<<TT * 16, 256, PG_SMEM>>>(bih, bhh);
    lstm_rec_mma<<<REC_CTAS, 256, REC_SMEM>>>(out, out_size);
    fc_kernel<<<TT, 320>>>(fcw, fcb, out);
}

// round 16
// speedup vs baseline: 1.3910x; 1.1116x over previous
#include <cuda_runtime.h>
#include <cuda_bf16.h>
#include <cuda_fp16.h>
#include <math.h>
#include <stdint.h>

// LSTM: T=1024, B=64, I=256, H=512, O=5
// out = [outputs (T*B*O) | h_T (B*H) | c_T (B*H)]

#define TT 1024
#define BB 64
#define II 256
#define HH 512
#define G4 2048
#define OO 5
#define REC_CTAS 128

// ---- device scratch ----
__device__ float g_xgT[(size_t)TT * G4 * BB];     // [T][4H][B]
__device__ float g_hsT[(size_t)TT * HH * BB];     // [T][H][B]
// Whh split-fp16 per rec-CTA tile: [(m*2+copy)*16 + r][512], r = gate*4+u
__device__ __half g_Awhh[128 * 2 * 16 * 512];
// h fp16 single plane, PADDED ldmatrix-ready, ping-pong: [pp 2][k 512][72]
__device__ __align__(16) __half g_hf16[2 * 512 * 72];
// Wih split-fp16: [copy 2][R 2048][k 256]
__device__ __half g_wih16[2 * 2048 * 256];
// x fp16 single plane, transposed per t: [t 1024][k 256][b 64]
__device__ __half g_x16[(size_t)1024 * 256 * 64];
__device__ unsigned g_bar_count;
__device__ volatile unsigned g_bar_gen;

__device__ __forceinline__ float sigf(float x) {
    return 1.0f / (1.0f + __expf(-x));
}
__device__ __forceinline__ float tanhfast(float x) {
    x = fminf(fmaxf(x, -15.0f), 15.0f);
    float e = __expf(2.0f * x);
    return __fdividef(e - 1.0f, e + 1.0f);
}

__device__ __forceinline__ void cpa16(uint32_t saddr, const void* gptr) {
    asm volatile("cp.async.cg.shared.global [%0], [%1], 16;"
                 :: "r"(saddr), "l"(gptr));
}
#define CP_COMMIT() asm volatile("cp.async.commit_group;")
#define CP_WAIT(n)  asm volatile("cp.async.wait_group %0;" :: "n"(n))

__device__ __forceinline__ void bulk_copy(uint32_t dst_smem, const void* src,
                                          uint32_t bytes, uint32_t mbar) {
    asm volatile(
        "cp.async.bulk.shared::cta.global.mbarrier::complete_tx::bytes "
        "[%0], [%1], %2, [%3];"
        :: "r"(dst_smem), "l"(src), "r"(bytes), "r"(mbar) : "memory");
}
#define MBAR_INIT(mb) \
    asm volatile("mbarrier.init.shared.b64 [%0], 1;" :: "r"(mb) : "memory")
#define MBAR_EXPECT_TX(mb, bytes) \
    asm volatile("mbarrier.arrive.expect_tx.shared.b64 _, [%0], %1;" \
                 :: "r"(mb), "r"(bytes) : "memory")
__device__ __forceinline__ void mbar_wait(uint32_t mb, uint32_t parity) {
    asm volatile(
        "{\n\t.reg .pred P;\n"
        "L_%=:\n\t"
        "mbarrier.try_wait.parity.acquire.cta.shared::cta.b64 P, [%0], %1;\n\t"
        "@P bra D_%=;\n\tbra L_%=;\n"
        "D_%=:\n\t}" :: "r"(mb), "r"(parity) : "memory");
}

#define LDSM_X4(r0,r1,r2,r3,addr) \
    asm volatile("ldmatrix.sync.aligned.m8n8.x4.shared.b16 {%0,%1,%2,%3}, [%4];" \
        : "=r"(r0),"=r"(r1),"=r"(r2),"=r"(r3) : "r"(addr))
#define LDSM_X2T(r0,r1,addr) \
    asm volatile("ldmatrix.sync.aligned.m8n8.x2.trans.shared.b16 {%0,%1}, [%2];" \
        : "=r"(r0),"=r"(r1) : "r"(addr))
// fp16 MMA
#define MMAH16816(d0,d1,d2,d3,a0,a1,a2,a3,b0,b1) \
    asm volatile("mma.sync.aligned.m16n8k16.row.col.f32.f16.f16.f32 " \
        "{%0,%1,%2,%3}, {%4,%5,%6,%7}, {%8,%9}, {%0,%1,%2,%3};" \
        : "+f"(d0),"+f"(d1),"+f"(d2),"+f"(d3) \
        : "r"(a0),"r"(a1),"r"(a2),"r"(a3),"r"(b0),"r"(b1))

// Grid barrier. Internal syncthreads -> fence(tid0) -> arrive provides the
// release chain for all prior stores of the CTA (no per-thread fences needed).
__device__ __forceinline__ void grid_sync() {
    __syncthreads();
    if (threadIdx.x == 0) {
        unsigned old = g_bar_gen;
        __threadfence();
        unsigned t = atomicAdd(&g_bar_count, 1u);
        if (t == REC_CTAS - 1) {
            atomicExch(&g_bar_count, 0u);
            __threadfence();
            g_bar_gen = old + 1u;
        } else {
            while (g_bar_gen == old) { }
            __threadfence();
        }
    }
    __syncthreads();
}

// ============================================================================
// Kernel P1: Whh -> split-fp16 rec tiles (R = gate*512 + m*4 + u)
// ============================================================================
__global__ void prep_whh(const float* __restrict__ Whh) {
    int R = blockIdx.x;
    int gate = R >> 9, rem = R & 511;
    int m = rem >> 2, u = rem & 3;
    int r = gate * 4 + u;
    for (int k = threadIdx.x; k < HH; k += blockDim.x) {
        float w = Whh[(size_t)R * HH + k];
        __half hi = __float2half(w);
        __half lo = __float2half(w - __half2float(hi));
        g_Awhh[((size_t)(m * 2 + 0) * 16 + r) * HH + k] = hi;
        g_Awhh[((size_t)(m * 2 + 1) * 16 + r) * HH + k] = lo;
    }
}

// ============================================================================
// Kernel P2: Wih -> split-fp16 [copy][R][k]
// ============================================================================
__global__ void prep_wih(const float* __restrict__ Wih) {
    int R = blockIdx.x;
    for (int k = threadIdx.x; k < II; k += blockDim.x) {
        float w = Wih[(size_t)R * II + k];
        __half hi = __float2half(w);
        __half lo = __float2half(w - __half2float(hi));
        g_wih16[(size_t)R * II + k] = hi;
        g_wih16[(size_t)(2048 + R) * II + k] = lo;
    }
}

// ============================================================================
// Kernel P3: x[t] -> fp16 single plane, transposed [t][k][b]
// ============================================================================
__global__ void prep_x(const float* __restrict__ x) {
    __shared__ float xs[64 * 257];
    const int t = blockIdx.x, tid = threadIdx.x;
    for (int idx = tid; idx < 64 * 64; idx += 256) {
        int b = idx >> 6, i = idx & 63;
        float4 v = *(const float4*)(x + ((size_t)t * BB + b) * II + i * 4);
        xs[b * 257 + i*4 + 0] = v.x; xs[b * 257 + i*4 + 1] = v.y;
        xs[b * 257 + i*4 + 2] = v.z; xs[b * 257 + i*4 + 3] = v.w;
    }
    __syncthreads();
    __half* dst = g_x16 + (size_t)t * (256 * 64);
    for (int idx = tid; idx < 256 * 64; idx += 256) {
        int k = idx >> 6, b = idx & 63;
        dst[(size_t)k * 64 + b] = __float2half(xs[b * 257 + k]);
    }
}

// ============================================================================
// Kernel 1: pregemm via fp16 HMMA, 2-term (w hi/lo x single x plane).
// grid = 1024(t) x 16(mbG). CTA: M=128 rows, N=64, K=256 in 4 chunks, dbuf.
// ============================================================================
#define PG_ACOPY 18432            // 128 rows * 144B
#define PG_AOFF  0
#define PG_BOFF  36864            // 2*PG_ACOPY
#define PG_BONE  9216             // 64 rows * 144B (single copy)
#define PG_CHUNK 46080
#define PG_BIAS  (2 * PG_CHUNK)   // 92160
#define PG_SMEM  (PG_BIAS + 512 + 256)

__device__ __forceinline__ void pg_stage(uint32_t sb, int buf, int mbG, int t,
                                         int kc, int tid) {
    uint32_t dst = sb + buf * PG_CHUNK;
    #pragma unroll
    for (int j = 0; j < 8; j++) {       // A: 2048 16B-chunks (2 copies)
        int idx = j * 256 + tid;
        int c2 = idx >> 10, rem = idx & 1023;
        int r = rem >> 3, i = rem & 7;
        cpa16(dst + PG_AOFF + c2 * PG_ACOPY + r * 144 + i * 16,
              g_wih16 + ((size_t)(c2 * 2048 + mbG * 128 + r)) * II + kc * 64 + i * 8);
    }
    #pragma unroll
    for (int j = 0; j < 2; j++) {       // B: 512 16B-chunks (single copy)
        int idx = j * 256 + tid;
        int k = idx >> 3, i = idx & 7;
        cpa16(dst + PG_BOFF + k * 144 + i * 16,
              g_x16 + ((size_t)t * 256 + kc * 64 + k) * 64 + i * 8);
    }
    CP_COMMIT();
}

__global__ void __launch_bounds__(256, 1) pregemm_mma(
    const float* __restrict__ bih, const float* __restrict__ bhh)
{
    extern __shared__ char smraw[];
    uint32_t sb0 = (uint32_t)__cvta_generic_to_shared(smraw);
    uint32_t sb  = (sb0 + 127u) & ~127u;
    char* smem = smraw + (sb - sb0);
    float* bsm = (float*)(smem + PG_BIAS);

    const int t   = blockIdx.x >> 4;
    const int mbG = blockIdx.x & 15;
    const int tid = threadIdx.x;
    const int wid = tid >> 5;
    const int lane = tid & 31;

    if (tid < 128) {
        int R = mbG * 128 + tid;
        bsm[tid] = bih[R] + bhh[R];
    }

    pg_stage(sb, 0, mbG, t, 0, tid);
    pg_stage(sb, 1, mbG, t, 1, tid);

    float d[8][4];
    #pragma unroll
    for (int i = 0; i < 8; i++)
        #pragma unroll
        for (int j = 0; j < 4; j++) d[i][j] = 0.0f;

    const uint32_t aRel = (uint32_t)(lane & 15) * 144 + (uint32_t)(lane >> 4) * 16;
    const uint32_t bRel = (uint32_t)(lane & 15) * 144 + (uint32_t)wid * 16;

    #pragma unroll
    for (int c = 0; c < 4; c++) {
        if (c < 3) CP_WAIT(1); else CP_WAIT(0);
        __syncthreads();
        uint32_t buf = sb + (c & 1) * PG_CHUNK;
        uint32_t aB = buf + PG_AOFF + aRel;
        uint32_t bB = buf + PG_BOFF + bRel;
        #pragma unroll
        for (int ks = 0; ks < 4; ks++) {
            uint32_t b0, b1;
            LDSM_X2T(b0, b1, bB + ks * 2304);
            #pragma unroll
            for (int mb = 0; mb < 8; mb++) {
                uint32_t ah0,ah1,ah2,ah3, al0,al1,al2,al3;
                LDSM_X4(ah0,ah1,ah2,ah3, aB + mb * 2304 + ks * 32);
                LDSM_X4(al0,al1,al2,al3, aB + PG_ACOPY + mb * 2304 + ks * 32);
                MMAH16816(d[mb][0],d[mb][1],d[mb][2],d[mb][3], ah0,ah1,ah2,ah3, b0,b1);
                MMAH16816(d[mb][0],d[mb][1],d[mb][2],d[mb][3], al0,al1,al2,al3, b0,b1);
            }
        }
        __syncthreads();
        if (c < 2) pg_stage(sb, c & 1, mbG, t, c + 2, tid);
    }

    float* outp = g_xgT + (size_t)t * (G4 * BB);
    const int c0 = wid * 8 + (lane & 3) * 2;
    #pragma unroll
    for (int mb = 0; mb < 8; mb++) {
        int r0 = mb * 16 + (lane >> 2);
        int R0 = mbG * 128 + r0;
        float b0 = bsm[r0], b1 = bsm[r0 + 8];
        *(float2*)(outp + (size_t)R0 * BB + c0) =
            make_float2(d[mb][0] + b0, d[mb][1] + b0);
        *(float2*)(outp + (size_t)(R0 + 8) * BB + c0) =
            make_float2(d[mb][2] + b1, d[mb][3] + b1);
    }
}

// ============================================================================
// Kernel 2: persistent fp16-HMMA recurrence, 128 CTAs x M=16.
// h = single fp16 plane staged as FOUR 18KB chunks on 4 mbarriers.
// ============================================================================
#define HSM_OFF   0
#define HSM_PLANE 73728           // 512 rows * 144B
#define HSM_CHUNK 18432           // 128 rows
#define ASM_OFF   73728
#define ASM_COPY  16640           // 16 rows * 1040B
#define GSM_OFF   107008
#define GSM_STR   66
#define CSM_OFF   111232
#define MBAR_OFF  112256
#define REC_SMEM  (112384 + 256)

__global__ void __launch_bounds__(256, 1) lstm_rec_mma(
    float* __restrict__ d_out, int out_size)
{
    extern __shared__ char smraw[];
    uint32_t sb0 = (uint32_t)__cvta_generic_to_shared(smraw);
    uint32_t sb  = (sb0 + 127u) & ~127u;
    char* smem = smraw + (sb - sb0);

    float* gsm = (float*)(smem + GSM_OFF);
    float* csm = (float*)(smem + CSM_OFF);

    const int m    = blockIdx.x;
    const int tid  = threadIdx.x;
    const int wid  = tid >> 5;
    const int lane = tid & 31;
    const int b    = tid & 63;
    const int u    = tid >> 6;

    // one-time: A tiles (fp16 hi/lo) -> smem, 1040B row stride
    for (int idx = tid; idx < 2 * 16 * 64; idx += 256) {
        int c = idx >> 10, rem = idx & 1023;
        int r = rem >> 6, i = rem & 63;
        uint4 v = *(const uint4*)(g_Awhh + ((size_t)(m*2+c)*16 + r) * HH + i*8);
        *(uint4*)(smem + ASM_OFF + c*ASM_COPY + r*1040 + i*16) = v;
    }
    // zero fp16 h ping-pong: 2*512*72 halves = 9216 uint4
    for (int i = m * 256 + tid; i < 9216; i += REC_CTAS * 256)
        ((uint4*)g_hf16)[i] = make_uint4(0, 0, 0, 0);
    csm[u * 64 + b] = 0.0f;
    if (tid == 0) {
        #pragma unroll
        for (int c = 0; c < 4; c++) MBAR_INIT(sb + MBAR_OFF + c * 8);
    }
    grid_sync();   // internal fence chain publishes the zeroed h planes

    const uint32_t aBase = sb + ASM_OFF + (uint32_t)(lane & 15) * 1040
                         + (uint32_t)(lane >> 4) * 16;
    const uint32_t bBase = sb + HSM_OFF + (uint32_t)(lane & 15) * 144
                         + (uint32_t)wid * 16;

    int cur = 0;
    for (int step = 0; step < TT; step++) {
        const __half* hsrc = g_hf16 + (size_t)cur * (512 * 72);
        if (tid == 0) {
            #pragma unroll
            for (int c = 0; c < 4; c++) {
                uint32_t mb = sb + MBAR_OFF + c * 8;
                MBAR_EXPECT_TX(mb, HSM_CHUNK);
                bulk_copy(sb + HSM_OFF + c * HSM_CHUNK,
                          hsrc + (size_t)c * 128 * 72, HSM_CHUNK, mb);
            }
        }

        const float* xgs = g_xgT + (size_t)step * (G4 * BB);
        int gu = m * 4 + u;
        float xg0 = __ldcs(xgs + (size_t)(0*HH + gu) * BB + b);
        float xg1 = __ldcs(xgs + (size_t)(1*HH + gu) * BB + b);
        float xg2 = __ldcs(xgs + (size_t)(2*HH + gu) * BB + b);
        float xg3 = __ldcs(xgs + (size_t)(3*HH + gu) * BB + b);

        float d0 = 0.f, d1 = 0.f, d2 = 0.f, d3 = 0.f;

        #pragma unroll
        for (int c = 0; c < 4; c++) {
            mbar_wait(sb + MBAR_OFF + c * 8, step & 1);
            #pragma unroll
            for (int ks = c * 8; ks < c * 8 + 8; ks++) {
                uint32_t ah0,ah1,ah2,ah3, al0,al1,al2,al3, bh0,bh1;
                LDSM_X4(ah0,ah1,ah2,ah3, aBase + ks*32);
                LDSM_X4(al0,al1,al2,al3, aBase + ASM_COPY + ks*32);
                LDSM_X2T(bh0,bh1, bBase + ks*2304);
                MMAH16816(d0,d1,d2,d3, ah0,ah1,ah2,ah3, bh0,bh1);
                MMAH16816(d0,d1,d2,d3, al0,al1,al2,al3, bh0,bh1);
            }
        }

        {
            int r0 = lane >> 2;
            int cB = wid * 8 + (lane & 3) * 2;
            *(float2*)&gsm[r0 * GSM_STR + cB]       = make_float2(d0, d1);
            *(float2*)&gsm[(r0 + 8) * GSM_STR + cB] = make_float2(d2, d3);
        }
        __syncthreads();

        {
            float p0 = gsm[(0*4 + u) * GSM_STR + b] + xg0;
            float p1 = gsm[(1*4 + u) * GSM_STR + b] + xg1;
            float p2 = gsm[(2*4 + u) * GSM_STR + b] + xg2;
            float p3 = gsm[(3*4 + u) * GSM_STR + b] + xg3;
            float ig = sigf(p0), fg = sigf(p1);
            float gg = tanhfast(p2), og = sigf(p3);
            float c  = fmaf(fg, csm[u * 64 + b], ig * gg);
            float h  = og * tanhfast(c);
            csm[u * 64 + b] = c;
            __stcs(&g_hsT[(size_t)step * (HH*BB) + (size_t)gu * BB + b], h);
            int nxt = cur ^ 1;
            __half* hw = g_hf16 + (size_t)nxt * (512 * 72);
            hw[(size_t)gu * 72 + b] = __float2half(h);
            if (step == TT - 1 && out_size >= TT*BB*OO + 2*BB*HH) {
                d_out[TT*BB*OO + (size_t)b * HH + gu] = h;
                d_out[TT*BB*OO + BB*HH + (size_t)b * HH + gu] = c;
            }
        }
        grid_sync();   // release: h stores published via internal fence chain
        cur ^= 1;
    }
}

// ============================================================================
// Kernel 3: FC epilogue
// ============================================================================
__global__ void __launch_bounds__(320) fc_kernel(
    const float* __restrict__ fcw, const float* __restrict__ fcb,
    float* __restrict__ out)
{
    __shared__ float wsm[OO][HH];
    __shared__ float bsm[OO];
    const int t = blockIdx.x, tid = threadIdx.x;
    for (int s = tid; s < OO * HH; s += 320) wsm[s / HH][s % HH] = fcw[s];
    if (tid < OO) bsm[tid] = fcb[tid];
    __syncthreads();
    const int o = tid >> 6, b = tid & 63;
    const float* hp = g_hsT + (size_t)t * (HH * BB) + b;
    float acc = bsm[o];
    #pragma unroll 8
    for (int k = 0; k < HH; k++)
        acc = fmaf(__ldcs(hp + (size_t)k * BB), wsm[o][k], acc);
    out[(size_t)t * (BB * OO) + b * OO + o] = acc;
}

// ============================================================================
extern "C" void kernel_launch(void* const* d_in, const int* in_sizes, int n_in,
                              void* d_out, int out_size) {
    const float* x   = (const float*)d_in[0];
    const float* Wih = (const float*)d_in[1];
    const float* Whh = (const float*)d_in[2];
    const float* bih = (const float*)d_in[3];
    const float* bhh = (const float*)d_in[4];
    const float* fcw = (const float*)d_in[5];
    const float* fcb = (const float*)d_in[6];
    float* out = (float*)d_out;

    cudaFuncSetAttribute(lstm_rec_mma,
                         cudaFuncAttributeMaxDynamicSharedMemorySize, REC_SMEM);
    cudaFuncSetAttribute(pregemm_mma,
                         cudaFuncAttributeMaxDynamicSharedMemorySize, PG_SMEM);

    prep_whh<<<G4, 128>>>(Whh);
    prep_wih<<<G4, 128>>>(Wih);
    prep_x<<<TT, 256>>>(x);
    pregemm_mma<<<TT * 16, 256, PG_SMEM>>>(bih, bhh);
    lstm_rec_mma<<<REC_CTAS, 256, REC_SMEM>>>(out, out_size);
    fc_kernel<<<TT, 320>>>(fcw, fcb, out);
}